// round 13
// baseline (speedup 1.0000x reference)
#include <cuda_runtime.h>
#include <cuda_bf16.h>
#include <math.h>
#include <stdint.h>

#define N_NODES 50000
#define N_EDGES 800000
#define DIN 512
#define DH 128
#define DOUTC 7
#define BN_EPS 1e-5f
#define SCAN_T 1024

// ---------------- scratch (no cudaMalloc allowed) ----------------
__device__ int   g_cnt[N_NODES];
__device__ int   g_row[N_NODES];
__device__ int   g_cursor[N_NODES];
__device__ __align__(8) int2 g_csr[N_EDGES];   // .x = src, .y = weight bits
__device__ float g_dinv[N_NODES];
__device__ __align__(16) float g_h1[N_NODES * DH];
__device__ __align__(16) float g_h2[N_NODES * DH];
__device__ float g_alpha1[DH];
__device__ float g_beta1[DH];
__device__ float g_alpha2[DH];
__device__ float g_beta2[DH];
__device__ __align__(16) __nv_bfloat16 g_B1H[DH * DIN];
__device__ __align__(16) __nv_bfloat16 g_B1L[DH * DIN];
__device__ __align__(16) __nv_bfloat16 g_B2H[DH * DH];
__device__ __align__(16) __nv_bfloat16 g_B2L[DH * DH];

// ---------------- CSR build ----------------
__global__ void k_zero() {
    int i = blockIdx.x * blockDim.x + threadIdx.x;
    if (i < N_NODES) g_cnt[i] = 0;
}

__global__ void k_hist(const int* __restrict__ ei) {
    int e = blockIdx.x * blockDim.x + threadIdx.x;
    if (e < N_EDGES) atomicAdd(&g_cnt[ei[N_EDGES + e]], 1);
}

__global__ void k_dinv() {
    int i = blockIdx.x * blockDim.x + threadIdx.x;
    if (i < N_NODES) g_dinv[i] = rsqrtf((float)(g_cnt[i] + 1));
}

__global__ __launch_bounds__(SCAN_T) void k_scan() {
    __shared__ int sums[SCAN_T];
    int t = threadIdx.x;
    const int CH = (N_NODES + SCAN_T - 1) / SCAN_T;
    int start = t * CH;
    int end = start + CH; if (end > N_NODES) end = N_NODES;
    int s = 0;
    for (int i = start; i < end; i++) s += g_cnt[i];
    sums[t] = s;
    __syncthreads();
    for (int off = 1; off < SCAN_T; off <<= 1) {
        int v = (t >= off) ? sums[t - off] : 0;
        __syncthreads();
        sums[t] += v;
        __syncthreads();
    }
    int run = (t == 0) ? 0 : sums[t - 1];
    for (int i = start; i < end; i++) {
        g_row[i] = run;
        g_cursor[i] = run;
        run += g_cnt[i];
    }
}

__global__ void k_fill(const int* __restrict__ ei) {
    int e = blockIdx.x * blockDim.x + threadIdx.x;
    if (e < N_EDGES) {
        int s = ei[e];
        int d = ei[N_EDGES + e];
        int p = atomicAdd(&g_cursor[d], 1);
        g_csr[p] = make_int2(s, __float_as_int(g_dinv[s] * g_dinv[d]));
    }
}

// ---------------- BN affines ----------------
__global__ void k_bnparam2(const float* __restrict__ b1, const float* __restrict__ g1,
                           const float* __restrict__ be1, const float* __restrict__ rm1,
                           const float* __restrict__ rv1,
                           const float* __restrict__ b2, const float* __restrict__ g2,
                           const float* __restrict__ be2, const float* __restrict__ rm2,
                           const float* __restrict__ rv2) {
    int c = threadIdx.x;
    if (c < DH) {
        float a = g1[c] * rsqrtf(rv1[c] + BN_EPS);
        g_alpha1[c] = a;
        g_beta1[c]  = (b1[c] - rm1[c]) * a + be1[c];
    } else {
        int d = c - DH;
        float a = g2[d] * rsqrtf(rv2[d] + BN_EPS);
        g_alpha2[d] = a;
        g_beta2[d]  = (b2[d] - rm2[d]) * a + be2[d];
    }
}

// ---------------- weight transpose + bf16 split ----------------
template<int K>
__global__ void k_prepB(const float* __restrict__ W,
                        __nv_bfloat16* __restrict__ BtH, __nv_bfloat16* __restrict__ BtL) {
    int idx = blockIdx.x * blockDim.x + threadIdx.x;
    if (idx < DH * K) {
        int n = idx / K, k = idx % K;
        float w = W[k * DH + n];
        __nv_bfloat16 h = __float2bfloat16(w);
        __nv_bfloat16 l = __float2bfloat16(w - __bfloat162float(h));
        BtH[idx] = h;
        BtL[idx] = l;
    }
}

// ---------------- bf16 MMA m16n8k16 ----------------
__device__ __forceinline__ void mma_bf16(float* d, const unsigned* a, const unsigned* b) {
    asm volatile(
        "mma.sync.aligned.m16n8k16.row.col.f32.bf16.bf16.f32 "
        "{%0,%1,%2,%3}, {%4,%5,%6,%7}, {%8,%9}, {%0,%1,%2,%3};"
        : "+f"(d[0]), "+f"(d[1]), "+f"(d[2]), "+f"(d[3])
        : "r"(a[0]), "r"(a[1]), "r"(a[2]), "r"(a[3]), "r"(b[0]), "r"(b[1]));
}

__device__ __forceinline__ void packsplit(float x, float y, unsigned& hi, unsigned& lo) {
    __nv_bfloat162 h = __floats2bfloat162_rn(x, y);
    hi = *(unsigned*)&h;
    float hx = __bfloat162float(__low2bfloat16(h));
    float hy = __bfloat162float(__high2bfloat16(h));
    __nv_bfloat162 l = __floats2bfloat162_rn(x - hx, y - hy);
    lo = *(unsigned*)&l;
}

__device__ __forceinline__ void cpa16(uint32_t dst, const void* src) {
    asm volatile("cp.async.cg.shared.global [%0], [%1], 16;" :: "r"(dst), "l"(src) : "memory");
}
__device__ __forceinline__ void cpa_commit() {
    asm volatile("cp.async.commit_group;" ::: "memory");
}

// ---------------- bf16x3 GEMM, cp.async 3-stage pipeline ----------------
// BM=128, BN=128, BK=16. 8 warps (4M x 2N), warp tile 32x64.
// Dynamic smem: A fp32 [3][128*24], Bh/Bl u32 [3][128*12] = 72 KB.
#define ASTR 24
#define BSTR 12
#define A_ST (128 * ASTR)            // floats per A stage
#define B_ST (128 * BSTR)            // u32 per B stage
#define GEMM_SMEM (3 * A_ST * 4 + 3 * B_ST * 4 * 2)

__global__ __launch_bounds__(256, 2) void gemm_cp(
    const float* __restrict__ A,
    const __nv_bfloat16* __restrict__ BtH, const __nv_bfloat16* __restrict__ BtL,
    float* __restrict__ C, int M, int K)
{
    extern __shared__ char smem[];
    float*    Afp = (float*)smem;                                  // [3][A_ST]
    unsigned* Bhs = (unsigned*)(smem + 3 * A_ST * 4);              // [3][B_ST]
    unsigned* Bls = (unsigned*)(smem + 3 * A_ST * 4 + 3 * B_ST * 4);

    int tid = threadIdx.x, wid = tid >> 5, lane = tid & 31;
    int wm = wid >> 1, wn = wid & 1;
    int g = lane >> 2, t4 = lane & 3;
    int m0 = blockIdx.x * 128;

    uint32_t aBase  = (uint32_t)__cvta_generic_to_shared(Afp);
    uint32_t bhBase = (uint32_t)__cvta_generic_to_shared(Bhs);
    uint32_t blBase = (uint32_t)__cvta_generic_to_shared(Bls);

    int rA = tid >> 2, cA = tid & 3;
    int rA2 = (tid + 256) >> 2, cA2 = (tid + 256) & 3;
    int rowA  = m0 + rA;  if (rowA  >= M) rowA  = M - 1;
    int rowA2 = m0 + rA2; if (rowA2 >= M) rowA2 = M - 1;
    int nB = tid >> 1, qB = tid & 1;

    auto issue = [&](int t, int st) {
        int k0 = t * 16;
        cpa16(aBase + (uint32_t)(st * A_ST + rA * ASTR + cA * 4) * 4,
              A + (size_t)rowA * K + k0 + cA * 4);
        cpa16(aBase + (uint32_t)(st * A_ST + rA2 * ASTR + cA2 * 4) * 4,
              A + (size_t)rowA2 * K + k0 + cA2 * 4);
        cpa16(bhBase + (uint32_t)(st * B_ST + nB * BSTR + qB * 4) * 4,
              BtH + (size_t)nB * K + k0 + qB * 8);
        cpa16(blBase + (uint32_t)(st * B_ST + nB * BSTR + qB * 4) * 4,
              BtL + (size_t)nB * K + k0 + qB * 8);
        cpa_commit();
    };

    float acc[2][8][4];
#pragma unroll
    for (int mt = 0; mt < 2; mt++)
#pragma unroll
        for (int nt = 0; nt < 8; nt++)
#pragma unroll
            for (int j = 0; j < 4; j++) acc[mt][nt][j] = 0.0f;

    int T = K / 16;
    issue(0, 0);
    issue(1, 1);

    for (int t = 0; t < T; t++) {
        int cur = t % 3;
        if (t + 2 < T) {
            issue(t + 2, (t + 2) % 3);
            asm volatile("cp.async.wait_group 2;" ::: "memory");
        } else if (t + 1 < T) {
            asm volatile("cp.async.wait_group 1;" ::: "memory");
        } else {
            asm volatile("cp.async.wait_group 0;" ::: "memory");
        }
        __syncthreads();

        const float* Ab = Afp + cur * A_ST;
        const unsigned* Bhb = Bhs + cur * B_ST;
        const unsigned* Blb = Bls + cur * B_ST;

        unsigned ah[2][4], al[2][4];
#pragma unroll
        for (int mt = 0; mt < 2; mt++) {
            int mb = wm * 32 + mt * 16;
            float2 p0 = *(const float2*)&Ab[(mb + g)     * ASTR + 2 * t4];
            float2 p1 = *(const float2*)&Ab[(mb + 8 + g) * ASTR + 2 * t4];
            float2 p2 = *(const float2*)&Ab[(mb + g)     * ASTR + 8 + 2 * t4];
            float2 p3 = *(const float2*)&Ab[(mb + 8 + g) * ASTR + 8 + 2 * t4];
            packsplit(p0.x, p0.y, ah[mt][0], al[mt][0]);
            packsplit(p1.x, p1.y, ah[mt][1], al[mt][1]);
            packsplit(p2.x, p2.y, ah[mt][2], al[mt][2]);
            packsplit(p3.x, p3.y, ah[mt][3], al[mt][3]);
        }
        unsigned bh[8][2];
#pragma unroll
        for (int nt = 0; nt < 8; nt++) {
            int n = wn * 64 + nt * 8 + g;
            bh[nt][0] = Bhb[n * BSTR + t4];
            bh[nt][1] = Bhb[n * BSTR + 4 + t4];
        }
#pragma unroll
        for (int nt = 0; nt < 8; nt++)
#pragma unroll
            for (int mt = 0; mt < 2; mt++) mma_bf16(acc[mt][nt], ah[mt], bh[nt]);
#pragma unroll
        for (int nt = 0; nt < 8; nt++)
#pragma unroll
            for (int mt = 0; mt < 2; mt++) mma_bf16(acc[mt][nt], al[mt], bh[nt]);
#pragma unroll
        for (int nt = 0; nt < 8; nt++) {
            unsigned bl[2];
            int n = wn * 64 + nt * 8 + g;
            bl[0] = Blb[n * BSTR + t4];
            bl[1] = Blb[n * BSTR + 4 + t4];
#pragma unroll
            for (int mt = 0; mt < 2; mt++) mma_bf16(acc[mt][nt], ah[mt], bl);
        }
        __syncthreads();
    }

#pragma unroll
    for (int mt = 0; mt < 2; mt++) {
        int row0 = m0 + wm * 32 + mt * 16 + g;
        int row1 = row0 + 8;
#pragma unroll
        for (int nt = 0; nt < 8; nt++) {
            int col = wn * 64 + nt * 8 + 2 * t4;
            if (row0 < M)
                *(float2*)(C + (size_t)row0 * 128 + col) = make_float2(acc[mt][nt][0], acc[mt][nt][1]);
            if (row1 < M)
                *(float2*)(C + (size_t)row1 * 128 + col) = make_float2(acc[mt][nt][2], acc[mt][nt][3]);
        }
    }
}

// ---------------- gather core: warp accumulates weighted neighbor rows (MLP 8) ----------------
__device__ __forceinline__ float4 agg_gather(const float* __restrict__ h, int n, int lane) {
    float dv = g_dinv[n];
    float sl = dv * dv;
    float4 acc = ((const float4*)(h + (size_t)n * DH))[lane];
    acc.x *= sl; acc.y *= sl; acc.z *= sl; acc.w *= sl;

    int e = g_row[n];
    int end = e + g_cnt[n];
    for (; e + 8 <= end; e += 8) {
        int2 c[8];
        float4 v[8];
#pragma unroll
        for (int j = 0; j < 8; j++) c[j] = g_csr[e + j];
#pragma unroll
        for (int j = 0; j < 8; j++)
            v[j] = ((const float4*)(h + (size_t)c[j].x * DH))[lane];
#pragma unroll
        for (int j = 0; j < 8; j++) {
            float w = __int_as_float(c[j].y);
            acc.x = fmaf(w, v[j].x, acc.x); acc.y = fmaf(w, v[j].y, acc.y);
            acc.z = fmaf(w, v[j].z, acc.z); acc.w = fmaf(w, v[j].w, acc.w);
        }
    }
    if (e + 4 <= end) {
        int2 c[4];
        float4 v[4];
#pragma unroll
        for (int j = 0; j < 4; j++) c[j] = g_csr[e + j];
#pragma unroll
        for (int j = 0; j < 4; j++)
            v[j] = ((const float4*)(h + (size_t)c[j].x * DH))[lane];
#pragma unroll
        for (int j = 0; j < 4; j++) {
            float w = __int_as_float(c[j].y);
            acc.x = fmaf(w, v[j].x, acc.x); acc.y = fmaf(w, v[j].y, acc.y);
            acc.z = fmaf(w, v[j].z, acc.z); acc.w = fmaf(w, v[j].w, acc.w);
        }
        e += 4;
    }
    for (; e < end; e++) {
        int2 c0 = g_csr[e];
        float w0 = __int_as_float(c0.y);
        float4 v0 = ((const float4*)(h + (size_t)c0.x * DH))[lane];
        acc.x = fmaf(w0, v0.x, acc.x); acc.y = fmaf(w0, v0.y, acc.y);
        acc.z = fmaf(w0, v0.z, acc.z); acc.w = fmaf(w0, v0.w, acc.w);
    }
    return acc;
}

// ---------------- layer-1 aggregation + affine1 + relu ----------------
__global__ __launch_bounds__(256) void k_agg1(
    const float* __restrict__ h, float* __restrict__ out)
{
    int n = (blockIdx.x * blockDim.x + threadIdx.x) >> 5;
    int lane = threadIdx.x & 31;
    if (n >= N_NODES) return;

    float4 acc = agg_gather(h, n, lane);
    float4 a  = ((const float4*)g_alpha1)[lane];
    float4 bt = ((const float4*)g_beta1)[lane];
    acc.x = fmaxf(fmaf(acc.x, a.x, bt.x), 0.f);
    acc.y = fmaxf(fmaf(acc.y, a.y, bt.y), 0.f);
    acc.z = fmaxf(fmaf(acc.z, a.z, bt.z), 0.f);
    acc.w = fmaxf(fmaf(acc.w, a.w, bt.w), 0.f);
    ((float4*)(out + (size_t)n * DH))[lane] = acc;
}

// ---------------- fused: layer-2 aggregation + affine2 + relu + FC + log_softmax ----------------
__global__ __launch_bounds__(256) void k_agg_fc(
    const float* __restrict__ h, const float* __restrict__ Wfc,
    const float* __restrict__ bfc, float* __restrict__ out)
{
    __shared__ float Ws[DH * DOUTC];
    __shared__ float bs[DOUTC];
    for (int i = threadIdx.x; i < DH * DOUTC; i += blockDim.x) Ws[i] = Wfc[i];
    if (threadIdx.x < DOUTC) bs[threadIdx.x] = bfc[threadIdx.x];
    __syncthreads();

    int n = (blockIdx.x * blockDim.x + threadIdx.x) >> 5;
    int lane = threadIdx.x & 31;
    if (n >= N_NODES) return;

    float4 v = agg_gather(h, n, lane);
    float4 a  = ((const float4*)g_alpha2)[lane];
    float4 bt = ((const float4*)g_beta2)[lane];
    v.x = fmaxf(fmaf(v.x, a.x, bt.x), 0.f);
    v.y = fmaxf(fmaf(v.y, a.y, bt.y), 0.f);
    v.z = fmaxf(fmaf(v.z, a.z, bt.z), 0.f);
    v.w = fmaxf(fmaf(v.w, a.w, bt.w), 0.f);

    const float* w0 = &Ws[(4 * lane + 0) * DOUTC];
    const float* w1 = &Ws[(4 * lane + 1) * DOUTC];
    const float* w2 = &Ws[(4 * lane + 2) * DOUTC];
    const float* w3 = &Ws[(4 * lane + 3) * DOUTC];
    float o[DOUTC];
#pragma unroll
    for (int q = 0; q < DOUTC; q++)
        o[q] = fmaf(v.x, w0[q], fmaf(v.y, w1[q], fmaf(v.z, w2[q], v.w * w3[q])));

#pragma unroll
    for (int off = 16; off; off >>= 1)
#pragma unroll
        for (int q = 0; q < DOUTC; q++)
            o[q] += __shfl_down_sync(0xffffffff, o[q], off);

    if (lane == 0) {
        float m = -INFINITY;
#pragma unroll
        for (int q = 0; q < DOUTC; q++) { o[q] += bs[q]; m = fmaxf(m, o[q]); }
        float s = 0.0f;
#pragma unroll
        for (int q = 0; q < DOUTC; q++) s += expf(o[q] - m);
        float lse = m + logf(s);
#pragma unroll
        for (int q = 0; q < DOUTC; q++)
            out[(size_t)n * DOUTC + q] = o[q] - lse;
    }
}

// ---------------- launch ----------------
extern "C" void kernel_launch(void* const* d_in, const int* in_sizes, int n_in,
                              void* d_out, int out_size) {
    const float* x   = (const float*)d_in[0];
    const int*   ei  = (const int*)d_in[1];
    const float* W1  = (const float*)d_in[2];
    const float* b1  = (const float*)d_in[3];
    const float* g1  = (const float*)d_in[4];
    const float* be1 = (const float*)d_in[5];
    const float* rm1 = (const float*)d_in[6];
    const float* rv1 = (const float*)d_in[7];
    const float* W2  = (const float*)d_in[8];
    const float* b2  = (const float*)d_in[9];
    const float* g2  = (const float*)d_in[10];
    const float* be2 = (const float*)d_in[11];
    const float* rm2 = (const float*)d_in[12];
    const float* rv2 = (const float*)d_in[13];
    const float* Wfc = (const float*)d_in[14];
    const float* bfc = (const float*)d_in[15];
    float* out = (float*)d_out;

    float *p_h1, *p_h2;
    __nv_bfloat16 *p_B1H, *p_B1L, *p_B2H, *p_B2L;
    cudaGetSymbolAddress((void**)&p_h1, g_h1);
    cudaGetSymbolAddress((void**)&p_h2, g_h2);
    cudaGetSymbolAddress((void**)&p_B1H, g_B1H);
    cudaGetSymbolAddress((void**)&p_B1L, g_B1L);
    cudaGetSymbolAddress((void**)&p_B2H, g_B2H);
    cudaGetSymbolAddress((void**)&p_B2L, g_B2L);

    static cudaStream_t s2 = nullptr;
    static cudaEvent_t evFork = nullptr, evJoin = nullptr;
    static bool attrDone = false;
    if (s2 == nullptr) {
        cudaStreamCreateWithFlags(&s2, cudaStreamNonBlocking);
        cudaEventCreateWithFlags(&evFork, cudaEventDisableTiming);
        cudaEventCreateWithFlags(&evJoin, cudaEventDisableTiming);
    }
    if (!attrDone) {
        cudaFuncSetAttribute((const void*)gemm_cp,
                             cudaFuncAttributeMaxDynamicSharedMemorySize, GEMM_SMEM);
        attrDone = true;
    }

    const int GEMM_BLOCKS = (N_NODES + 127) / 128;
    const int NODE_BLOCKS = (N_NODES + 255) / 256;
    const int EDGE_BLOCKS = (N_EDGES + 255) / 256;
    const int WARP_NODE_BLOCKS = (N_NODES + 7) / 8;

    // fork: CSR-build chain + weight prep on s2 (independent of GEMM1)
    cudaEventRecord(evFork, 0);
    cudaStreamWaitEvent(s2, evFork, 0);

    k_prepB<DIN><<<(DH * DIN + 255) / 256, 256>>>(W1, p_B1H, p_B1L);     // 0 (main)
    k_zero<<<NODE_BLOCKS, 256, 0, s2>>>();                               // 1
    k_hist<<<EDGE_BLOCKS, 256, 0, s2>>>(ei);                             // 2
    gemm_cp<<<GEMM_BLOCKS, 256, GEMM_SMEM>>>(x, p_B1H, p_B1L, p_h1,
                                             N_NODES, DIN);              // 3 (profiled)
    k_dinv<<<NODE_BLOCKS, 256, 0, s2>>>();                               // 4
    k_scan<<<1, SCAN_T, 0, s2>>>();                                      // 5
    k_fill<<<EDGE_BLOCKS, 256, 0, s2>>>(ei);                             // 6
    k_bnparam2<<<1, 256, 0, s2>>>(b1, g1, be1, rm1, rv1,
                                  b2, g2, be2, rm2, rv2);                // 7
    k_prepB<DH><<<(DH * DH + 255) / 256, 256, 0, s2>>>(W2, p_B2H, p_B2L);// 8 (s2)
    cudaEventRecord(evJoin, s2);
    cudaStreamWaitEvent(0, evJoin, 0);

    k_agg1<<<WARP_NODE_BLOCKS, 256>>>(p_h1, p_h2);                       // 9
    gemm_cp<<<GEMM_BLOCKS, 256, GEMM_SMEM>>>(p_h2, p_B2H, p_B2L, p_h1,
                                             N_NODES, DH);               // 10
    k_agg_fc<<<WARP_NODE_BLOCKS, 256>>>(p_h1, Wfc, bfc, out);            // 11
}

// round 14
// speedup vs baseline: 1.2640x; 1.2640x over previous
#include <cuda_runtime.h>
#include <cuda_bf16.h>
#include <cooperative_groups.h>
#include <math.h>
#include <stdint.h>

namespace cg = cooperative_groups;

#define N_NODES 50000
#define N_EDGES 800000
#define DIN 512
#define DH 128
#define DOUTC 7
#define BN_EPS 1e-5f
#define CSR_BLOCKS 64
#define CSR_THREADS 1024
#define CSR_CH ((N_NODES + CSR_BLOCKS - 1) / CSR_BLOCKS)   // 782

// ---------------- scratch (no cudaMalloc allowed) ----------------
__device__ int   g_cnt[N_NODES];
__device__ int   g_row[N_NODES];
__device__ int   g_cursor[N_NODES];
__device__ int   g_bsum[CSR_BLOCKS];
__device__ __align__(8) int2 g_csr[N_EDGES];   // .x = src, .y = weight bits
__device__ float g_dinv[N_NODES];
__device__ __align__(16) float g_h1[N_NODES * DH];
__device__ __align__(16) float g_h2[N_NODES * DH];
__device__ float g_alpha1[DH];
__device__ float g_beta1[DH];
__device__ float g_alpha2[DH];
__device__ float g_beta2[DH];
__device__ __align__(16) __nv_bfloat16 g_B1H[DH * DIN];
__device__ __align__(16) __nv_bfloat16 g_B1L[DH * DIN];
__device__ __align__(16) __nv_bfloat16 g_B2H[DH * DH];
__device__ __align__(16) __nv_bfloat16 g_B2L[DH * DH];

// ---------------- fused CSR build + BN params (cooperative) ----------------
__global__ void k_csr_coop(
    const int* __restrict__ ei,
    const float* __restrict__ b1, const float* __restrict__ g1,
    const float* __restrict__ be1, const float* __restrict__ rm1,
    const float* __restrict__ rv1,
    const float* __restrict__ b2, const float* __restrict__ g2,
    const float* __restrict__ be2, const float* __restrict__ rm2,
    const float* __restrict__ rv2)
{
    cg::grid_group grid = cg::this_grid();
    int tid = threadIdx.x, bid = blockIdx.x;
    int gt = bid * CSR_THREADS + tid;
    const int GT = CSR_BLOCKS * CSR_THREADS;

    // phase 0: zero counts + BN affines (block 0)
    for (int i = gt; i < N_NODES; i += GT) g_cnt[i] = 0;
    if (bid == 0 && tid < 2 * DH) {
        int c = tid;
        if (c < DH) {
            float a = g1[c] * rsqrtf(rv1[c] + BN_EPS);
            g_alpha1[c] = a;
            g_beta1[c]  = (b1[c] - rm1[c]) * a + be1[c];
        } else {
            int d = c - DH;
            float a = g2[d] * rsqrtf(rv2[d] + BN_EPS);
            g_alpha2[d] = a;
            g_beta2[d]  = (b2[d] - rm2[d]) * a + be2[d];
        }
    }
    grid.sync();

    // phase 1: histogram
    for (int e = gt; e < N_EDGES; e += GT) atomicAdd(&g_cnt[ei[N_EDGES + e]], 1);
    grid.sync();

    // phase 2: dinv + per-block inclusive scan of counts (contiguous chunks)
    __shared__ int sc[CSR_THREADS];
    int node = bid * CSR_CH + tid;          // tid < CSR_CH covers all nodes exactly once
    int v = 0;
    if (tid < CSR_CH && node < N_NODES) {
        v = g_cnt[node];
        g_dinv[node] = rsqrtf((float)(v + 1));
    }
    sc[tid] = v;
    __syncthreads();
    for (int off = 1; off < CSR_THREADS; off <<= 1) {
        int add = (tid >= off) ? sc[tid - off] : 0;
        __syncthreads();
        sc[tid] += add;
        __syncthreads();
    }
    int incl = sc[tid];
    if (tid == CSR_THREADS - 1) g_bsum[bid] = incl;
    grid.sync();

    // phase 3: block 0 exclusive-scans the 64 block sums
    if (bid == 0) {
        __shared__ int bs[CSR_BLOCKS];
        if (tid < CSR_BLOCKS) bs[tid] = g_bsum[tid];
        __syncthreads();
        if (tid == 0) {
            int run = 0;
            for (int i = 0; i < CSR_BLOCKS; i++) { int t = bs[i]; bs[i] = run; run += t; }
        }
        __syncthreads();
        if (tid < CSR_BLOCKS) g_bsum[tid] = bs[tid];
    }
    grid.sync();

    // phase 4: write row offsets + cursors
    if (tid < CSR_CH && node < N_NODES) {
        int row = g_bsum[bid] + incl - v;
        g_row[node] = row;
        g_cursor[node] = row;
    }
    grid.sync();

    // phase 5: fill CSR with packed (src, weight)
    for (int e = gt; e < N_EDGES; e += GT) {
        int s = ei[e];
        int d = ei[N_EDGES + e];
        int p = atomicAdd(&g_cursor[d], 1);
        g_csr[p] = make_int2(s, __float_as_int(g_dinv[s] * g_dinv[d]));
    }
}

// ---------------- weight transpose + bf16 split ----------------
template<int K>
__global__ void k_prepB(const float* __restrict__ W,
                        __nv_bfloat16* __restrict__ BtH, __nv_bfloat16* __restrict__ BtL) {
    int idx = blockIdx.x * blockDim.x + threadIdx.x;
    if (idx < DH * K) {
        int n = idx / K, k = idx % K;
        float w = W[k * DH + n];
        __nv_bfloat16 h = __float2bfloat16(w);
        __nv_bfloat16 l = __float2bfloat16(w - __bfloat162float(h));
        BtH[idx] = h;
        BtL[idx] = l;
    }
}

// ---------------- bf16 MMA m16n8k16 ----------------
__device__ __forceinline__ void mma_bf16(float* d, const unsigned* a, const unsigned* b) {
    asm volatile(
        "mma.sync.aligned.m16n8k16.row.col.f32.bf16.bf16.f32 "
        "{%0,%1,%2,%3}, {%4,%5,%6,%7}, {%8,%9}, {%0,%1,%2,%3};"
        : "+f"(d[0]), "+f"(d[1]), "+f"(d[2]), "+f"(d[3])
        : "r"(a[0]), "r"(a[1]), "r"(a[2]), "r"(a[3]), "r"(b[0]), "r"(b[1]));
}

__device__ __forceinline__ void packsplit(float x, float y, unsigned& hi, unsigned& lo) {
    __nv_bfloat162 h = __floats2bfloat162_rn(x, y);
    hi = *(unsigned*)&h;
    float hx = __bfloat162float(__low2bfloat16(h));
    float hy = __bfloat162float(__high2bfloat16(h));
    __nv_bfloat162 l = __floats2bfloat162_rn(x - hx, y - hy);
    lo = *(unsigned*)&l;
}

__device__ __forceinline__ void cpa16(uint32_t dst, const void* src) {
    asm volatile("cp.async.cg.shared.global [%0], [%1], 16;" :: "r"(dst), "l"(src) : "memory");
}
__device__ __forceinline__ void cpa_commit() {
    asm volatile("cp.async.commit_group;" ::: "memory");
}

// ---------------- bf16x3 GEMM, cp.async 3-stage pipeline (R13) ----------------
#define ASTR 24
#define BSTR 12
#define A_ST (128 * ASTR)
#define B_ST (128 * BSTR)
#define GEMM_SMEM (3 * A_ST * 4 + 3 * B_ST * 4 * 2)

__global__ __launch_bounds__(256, 2) void gemm_cp(
    const float* __restrict__ A,
    const __nv_bfloat16* __restrict__ BtH, const __nv_bfloat16* __restrict__ BtL,
    float* __restrict__ C, int M, int K)
{
    extern __shared__ char smem[];
    float*    Afp = (float*)smem;
    unsigned* Bhs = (unsigned*)(smem + 3 * A_ST * 4);
    unsigned* Bls = (unsigned*)(smem + 3 * A_ST * 4 + 3 * B_ST * 4);

    int tid = threadIdx.x, wid = tid >> 5, lane = tid & 31;
    int wm = wid >> 1, wn = wid & 1;
    int g = lane >> 2, t4 = lane & 3;
    int m0 = blockIdx.x * 128;

    uint32_t aBase  = (uint32_t)__cvta_generic_to_shared(Afp);
    uint32_t bhBase = (uint32_t)__cvta_generic_to_shared(Bhs);
    uint32_t blBase = (uint32_t)__cvta_generic_to_shared(Bls);

    int rA = tid >> 2, cA = tid & 3;
    int rA2 = (tid + 256) >> 2, cA2 = (tid + 256) & 3;
    int rowA  = m0 + rA;  if (rowA  >= M) rowA  = M - 1;
    int rowA2 = m0 + rA2; if (rowA2 >= M) rowA2 = M - 1;
    int nB = tid >> 1, qB = tid & 1;

    auto issue = [&](int t, int st) {
        int k0 = t * 16;
        cpa16(aBase + (uint32_t)(st * A_ST + rA * ASTR + cA * 4) * 4,
              A + (size_t)rowA * K + k0 + cA * 4);
        cpa16(aBase + (uint32_t)(st * A_ST + rA2 * ASTR + cA2 * 4) * 4,
              A + (size_t)rowA2 * K + k0 + cA2 * 4);
        cpa16(bhBase + (uint32_t)(st * B_ST + nB * BSTR + qB * 4) * 4,
              BtH + (size_t)nB * K + k0 + qB * 8);
        cpa16(blBase + (uint32_t)(st * B_ST + nB * BSTR + qB * 4) * 4,
              BtL + (size_t)nB * K + k0 + qB * 8);
        cpa_commit();
    };

    float acc[2][8][4];
#pragma unroll
    for (int mt = 0; mt < 2; mt++)
#pragma unroll
        for (int nt = 0; nt < 8; nt++)
#pragma unroll
            for (int j = 0; j < 4; j++) acc[mt][nt][j] = 0.0f;

    int T = K / 16;
    issue(0, 0);
    issue(1, 1);

    for (int t = 0; t < T; t++) {
        int cur = t % 3;
        if (t + 2 < T) {
            issue(t + 2, (t + 2) % 3);
            asm volatile("cp.async.wait_group 2;" ::: "memory");
        } else if (t + 1 < T) {
            asm volatile("cp.async.wait_group 1;" ::: "memory");
        } else {
            asm volatile("cp.async.wait_group 0;" ::: "memory");
        }
        __syncthreads();

        const float* Ab = Afp + cur * A_ST;
        const unsigned* Bhb = Bhs + cur * B_ST;
        const unsigned* Blb = Bls + cur * B_ST;

        unsigned ah[2][4], al[2][4];
#pragma unroll
        for (int mt = 0; mt < 2; mt++) {
            int mb = wm * 32 + mt * 16;
            float2 p0 = *(const float2*)&Ab[(mb + g)     * ASTR + 2 * t4];
            float2 p1 = *(const float2*)&Ab[(mb + 8 + g) * ASTR + 2 * t4];
            float2 p2 = *(const float2*)&Ab[(mb + g)     * ASTR + 8 + 2 * t4];
            float2 p3 = *(const float2*)&Ab[(mb + 8 + g) * ASTR + 8 + 2 * t4];
            packsplit(p0.x, p0.y, ah[mt][0], al[mt][0]);
            packsplit(p1.x, p1.y, ah[mt][1], al[mt][1]);
            packsplit(p2.x, p2.y, ah[mt][2], al[mt][2]);
            packsplit(p3.x, p3.y, ah[mt][3], al[mt][3]);
        }
        unsigned bh[8][2];
#pragma unroll
        for (int nt = 0; nt < 8; nt++) {
            int n = wn * 64 + nt * 8 + g;
            bh[nt][0] = Bhb[n * BSTR + t4];
            bh[nt][1] = Bhb[n * BSTR + 4 + t4];
        }
#pragma unroll
        for (int nt = 0; nt < 8; nt++)
#pragma unroll
            for (int mt = 0; mt < 2; mt++) mma_bf16(acc[mt][nt], ah[mt], bh[nt]);
#pragma unroll
        for (int nt = 0; nt < 8; nt++)
#pragma unroll
            for (int mt = 0; mt < 2; mt++) mma_bf16(acc[mt][nt], al[mt], bh[nt]);
#pragma unroll
        for (int nt = 0; nt < 8; nt++) {
            unsigned bl[2];
            int n = wn * 64 + nt * 8 + g;
            bl[0] = Blb[n * BSTR + t4];
            bl[1] = Blb[n * BSTR + 4 + t4];
#pragma unroll
            for (int mt = 0; mt < 2; mt++) mma_bf16(acc[mt][nt], ah[mt], bl);
        }
        __syncthreads();
    }

#pragma unroll
    for (int mt = 0; mt < 2; mt++) {
        int row0 = m0 + wm * 32 + mt * 16 + g;
        int row1 = row0 + 8;
#pragma unroll
        for (int nt = 0; nt < 8; nt++) {
            int col = wn * 64 + nt * 8 + 2 * t4;
            if (row0 < M)
                *(float2*)(C + (size_t)row0 * 128 + col) = make_float2(acc[mt][nt][0], acc[mt][nt][1]);
            if (row1 < M)
                *(float2*)(C + (size_t)row1 * 128 + col) = make_float2(acc[mt][nt][2], acc[mt][nt][3]);
        }
    }
}

// ---------------- gather core (R13, unchanged for clean profile) ----------------
__device__ __forceinline__ float4 agg_gather(const float* __restrict__ h, int n, int lane) {
    float dv = g_dinv[n];
    float sl = dv * dv;
    float4 acc = ((const float4*)(h + (size_t)n * DH))[lane];
    acc.x *= sl; acc.y *= sl; acc.z *= sl; acc.w *= sl;

    int e = g_row[n];
    int end = e + g_cnt[n];
    for (; e + 8 <= end; e += 8) {
        int2 c[8];
        float4 v[8];
#pragma unroll
        for (int j = 0; j < 8; j++) c[j] = g_csr[e + j];
#pragma unroll
        for (int j = 0; j < 8; j++)
            v[j] = ((const float4*)(h + (size_t)c[j].x * DH))[lane];
#pragma unroll
        for (int j = 0; j < 8; j++) {
            float w = __int_as_float(c[j].y);
            acc.x = fmaf(w, v[j].x, acc.x); acc.y = fmaf(w, v[j].y, acc.y);
            acc.z = fmaf(w, v[j].z, acc.z); acc.w = fmaf(w, v[j].w, acc.w);
        }
    }
    if (e + 4 <= end) {
        int2 c[4];
        float4 v[4];
#pragma unroll
        for (int j = 0; j < 4; j++) c[j] = g_csr[e + j];
#pragma unroll
        for (int j = 0; j < 4; j++)
            v[j] = ((const float4*)(h + (size_t)c[j].x * DH))[lane];
#pragma unroll
        for (int j = 0; j < 4; j++) {
            float w = __int_as_float(c[j].y);
            acc.x = fmaf(w, v[j].x, acc.x); acc.y = fmaf(w, v[j].y, acc.y);
            acc.z = fmaf(w, v[j].z, acc.z); acc.w = fmaf(w, v[j].w, acc.w);
        }
        e += 4;
    }
    for (; e < end; e++) {
        int2 c0 = g_csr[e];
        float w0 = __int_as_float(c0.y);
        float4 v0 = ((const float4*)(h + (size_t)c0.x * DH))[lane];
        acc.x = fmaf(w0, v0.x, acc.x); acc.y = fmaf(w0, v0.y, acc.y);
        acc.z = fmaf(w0, v0.z, acc.z); acc.w = fmaf(w0, v0.w, acc.w);
    }
    return acc;
}

// ---------------- layer-1 aggregation + affine1 + relu ----------------
__global__ __launch_bounds__(256) void k_agg1(
    const float* __restrict__ h, float* __restrict__ out)
{
    int n = (blockIdx.x * blockDim.x + threadIdx.x) >> 5;
    int lane = threadIdx.x & 31;
    if (n >= N_NODES) return;

    float4 acc = agg_gather(h, n, lane);
    float4 a  = ((const float4*)g_alpha1)[lane];
    float4 bt = ((const float4*)g_beta1)[lane];
    acc.x = fmaxf(fmaf(acc.x, a.x, bt.x), 0.f);
    acc.y = fmaxf(fmaf(acc.y, a.y, bt.y), 0.f);
    acc.z = fmaxf(fmaf(acc.z, a.z, bt.z), 0.f);
    acc.w = fmaxf(fmaf(acc.w, a.w, bt.w), 0.f);
    ((float4*)(out + (size_t)n * DH))[lane] = acc;
}

// ---------------- fused: layer-2 aggregation + affine2 + relu + FC + log_softmax ----------------
__global__ __launch_bounds__(256) void k_agg_fc(
    const float* __restrict__ h, const float* __restrict__ Wfc,
    const float* __restrict__ bfc, float* __restrict__ out)
{
    __shared__ float Ws[DH * DOUTC];
    __shared__ float bs[DOUTC];
    for (int i = threadIdx.x; i < DH * DOUTC; i += blockDim.x) Ws[i] = Wfc[i];
    if (threadIdx.x < DOUTC) bs[threadIdx.x] = bfc[threadIdx.x];
    __syncthreads();

    int n = (blockIdx.x * blockDim.x + threadIdx.x) >> 5;
    int lane = threadIdx.x & 31;
    if (n >= N_NODES) return;

    float4 v = agg_gather(h, n, lane);
    float4 a  = ((const float4*)g_alpha2)[lane];
    float4 bt = ((const float4*)g_beta2)[lane];
    v.x = fmaxf(fmaf(v.x, a.x, bt.x), 0.f);
    v.y = fmaxf(fmaf(v.y, a.y, bt.y), 0.f);
    v.z = fmaxf(fmaf(v.z, a.z, bt.z), 0.f);
    v.w = fmaxf(fmaf(v.w, a.w, bt.w), 0.f);

    const float* w0 = &Ws[(4 * lane + 0) * DOUTC];
    const float* w1 = &Ws[(4 * lane + 1) * DOUTC];
    const float* w2 = &Ws[(4 * lane + 2) * DOUTC];
    const float* w3 = &Ws[(4 * lane + 3) * DOUTC];
    float o[DOUTC];
#pragma unroll
    for (int q = 0; q < DOUTC; q++)
        o[q] = fmaf(v.x, w0[q], fmaf(v.y, w1[q], fmaf(v.z, w2[q], v.w * w3[q])));

#pragma unroll
    for (int off = 16; off; off >>= 1)
#pragma unroll
        for (int q = 0; q < DOUTC; q++)
            o[q] += __shfl_down_sync(0xffffffff, o[q], off);

    if (lane == 0) {
        float m = -INFINITY;
#pragma unroll
        for (int q = 0; q < DOUTC; q++) { o[q] += bs[q]; m = fmaxf(m, o[q]); }
        float s = 0.0f;
#pragma unroll
        for (int q = 0; q < DOUTC; q++) s += expf(o[q] - m);
        float lse = m + logf(s);
#pragma unroll
        for (int q = 0; q < DOUTC; q++)
            out[(size_t)n * DOUTC + q] = o[q] - lse;
    }
}

// ---------------- launch ----------------
extern "C" void kernel_launch(void* const* d_in, const int* in_sizes, int n_in,
                              void* d_out, int out_size) {
    const float* x   = (const float*)d_in[0];
    const int*   ei  = (const int*)d_in[1];
    const float* W1  = (const float*)d_in[2];
    const float* b1  = (const float*)d_in[3];
    const float* g1  = (const float*)d_in[4];
    const float* be1 = (const float*)d_in[5];
    const float* rm1 = (const float*)d_in[6];
    const float* rv1 = (const float*)d_in[7];
    const float* W2  = (const float*)d_in[8];
    const float* b2  = (const float*)d_in[9];
    const float* g2  = (const float*)d_in[10];
    const float* be2 = (const float*)d_in[11];
    const float* rm2 = (const float*)d_in[12];
    const float* rv2 = (const float*)d_in[13];
    const float* Wfc = (const float*)d_in[14];
    const float* bfc = (const float*)d_in[15];
    float* out = (float*)d_out;

    float *p_h1, *p_h2;
    __nv_bfloat16 *p_B1H, *p_B1L, *p_B2H, *p_B2L;
    cudaGetSymbolAddress((void**)&p_h1, g_h1);
    cudaGetSymbolAddress((void**)&p_h2, g_h2);
    cudaGetSymbolAddress((void**)&p_B1H, g_B1H);
    cudaGetSymbolAddress((void**)&p_B1L, g_B1L);
    cudaGetSymbolAddress((void**)&p_B2H, g_B2H);
    cudaGetSymbolAddress((void**)&p_B2L, g_B2L);

    static cudaStream_t s2 = nullptr;
    static cudaEvent_t evFork = nullptr, evJoin = nullptr;
    static bool attrDone = false;
    if (s2 == nullptr) {
        cudaStreamCreateWithFlags(&s2, cudaStreamNonBlocking);
        cudaEventCreateWithFlags(&evFork, cudaEventDisableTiming);
        cudaEventCreateWithFlags(&evJoin, cudaEventDisableTiming);
    }
    if (!attrDone) {
        cudaFuncSetAttribute((const void*)gemm_cp,
                             cudaFuncAttributeMaxDynamicSharedMemorySize, GEMM_SMEM);
        attrDone = true;
    }

    const int GEMM_BLOCKS = (N_NODES + 127) / 128;
    const int WARP_NODE_BLOCKS = (N_NODES + 7) / 8;

    // --- submission order engineered so k_agg1 is call index 3 (profiled) ---
    // 0: prepB1 (main)
    k_prepB<DIN><<<(DH * DIN + 255) / 256, 256>>>(W1, p_B1H, p_B1L);

    // fork: fused CSR+BN build on s2 (hidden under gemm1)
    cudaEventRecord(evFork, 0);
    cudaStreamWaitEvent(s2, evFork, 0);
    {
        // 1: k_csr_coop (s2), cooperative
        const int* ei_ = ei;
        const float *b1_ = b1, *g1_ = g1, *be1_ = be1, *rm1_ = rm1, *rv1_ = rv1;
        const float *b2_ = b2, *g2_ = g2, *be2_ = be2, *rm2_ = rm2, *rv2_ = rv2;
        void* cargs[] = { (void*)&ei_,
                          (void*)&b1_, (void*)&g1_, (void*)&be1_, (void*)&rm1_, (void*)&rv1_,
                          (void*)&b2_, (void*)&g2_, (void*)&be2_, (void*)&rm2_, (void*)&rv2_ };
        cudaLaunchCooperativeKernel((void*)k_csr_coop,
                                    dim3(CSR_BLOCKS), dim3(CSR_THREADS), cargs, 0, s2);
    }
    cudaEventRecord(evJoin, s2);

    // 2: gemm1 (main)
    gemm_cp<<<GEMM_BLOCKS, 256, GEMM_SMEM>>>(x, p_B1H, p_B1L, p_h1, N_NODES, DIN);

    // join, then 3: k_agg1 (main)  <-- profiled launch
    cudaStreamWaitEvent(0, evJoin, 0);
    k_agg1<<<WARP_NODE_BLOCKS, 256>>>(p_h1, p_h2);

    // 4: prepB2, 5: gemm2, 6: agg_fc (main)
    k_prepB<DH><<<(DH * DH + 255) / 256, 256>>>(W2, p_B2H, p_B2L);
    gemm_cp<<<GEMM_BLOCKS, 256, GEMM_SMEM>>>(p_h2, p_B2H, p_B2L, p_h1, N_NODES, DH);
    k_agg_fc<<<WARP_NODE_BLOCKS, 256>>>(p_h1, Wfc, bfc, out);
}